// round 3
// baseline (speedup 1.0000x reference)
#include <cuda_runtime.h>
#include <math.h>

#define H     4096
#define NB    16
#define BS    256
#define TOPK  4
#define RANK  128
#define MT    128
#define MAXROWS 8192

// ---- device-global scratch (no allocations allowed) ----
__device__ int   g_counts[NB];
__device__ int   g_rows[NB * MAXROWS];
__device__ float g_wts [NB * MAXROWS];

__global__ void zero_counts_kernel() {
    if (threadIdx.x < NB) g_counts[threadIdx.x] = 0;
}

__device__ __forceinline__ float warp_sum(float v) {
    v += __shfl_down_sync(0xffffffffu, v, 16);
    v += __shfl_down_sync(0xffffffffu, v, 8);
    v += __shfl_down_sync(0xffffffffu, v, 4);
    v += __shfl_down_sync(0xffffffffu, v, 2);
    v += __shfl_down_sync(0xffffffffu, v, 1);
    return v;
}

// ---------------------------------------------------------------------------
// Kernel 1: per-row routing + residual copy (out = hidden).
// One CTA (256 threads) per row. Single pass computes sum, sumsq, and the
// three spatial-projection dots; ln dot uses dot(ln,w) = rstd*(dot(x,w)-mu*sum(w)).
// ---------------------------------------------------------------------------
__global__ void __launch_bounds__(256) route_kernel(
    const float* __restrict__ x, const float* __restrict__ prior,
    const float* __restrict__ sw, const float* __restrict__ sb,
    const float* __restrict__ rps_p, float* __restrict__ out)
{
    const int row = blockIdx.x;
    const float4* xv = (const float4*)(x + (size_t)row * H);
    float4*       ov = (float4*)(out + (size_t)row * H);
    const float4* w0 = (const float4*)(sw);
    const float4* w1 = (const float4*)(sw + H);
    const float4* w2 = (const float4*)(sw + 2 * H);

    float s = 0.f, s2 = 0.f, d0 = 0.f, d1 = 0.f, d2 = 0.f;
    float t0 = 0.f, t1 = 0.f, t2 = 0.f;

    #pragma unroll 4
    for (int i = threadIdx.x; i < H / 4; i += 256) {
        float4 v = xv[i];
        ov[i] = v;                       // fused residual copy
        float4 a = __ldg(&w0[i]);
        float4 b = __ldg(&w1[i]);
        float4 c = __ldg(&w2[i]);
        s  += (v.x + v.y) + (v.z + v.w);
        s2 += v.x * v.x + v.y * v.y + v.z * v.z + v.w * v.w;
        d0 += v.x * a.x + v.y * a.y + v.z * a.z + v.w * a.w;
        d1 += v.x * b.x + v.y * b.y + v.z * b.z + v.w * b.w;
        d2 += v.x * c.x + v.y * c.y + v.z * c.z + v.w * c.w;
        t0 += (a.x + a.y) + (a.z + a.w);
        t1 += (b.x + b.y) + (b.z + b.w);
        t2 += (c.x + c.y) + (c.z + c.w);
    }

    float vals[8] = {s, s2, d0, d1, d2, t0, t1, t2};
    __shared__ float red[8][8];
    const int wid = threadIdx.x >> 5, lane = threadIdx.x & 31;
    #pragma unroll
    for (int j = 0; j < 8; j++) vals[j] = warp_sum(vals[j]);
    if (lane == 0) {
        #pragma unroll
        for (int j = 0; j < 8; j++) red[wid][j] = vals[j];
    }
    __syncthreads();

    if (threadIdx.x == 0) {
        float r[8];
        #pragma unroll
        for (int j = 0; j < 8; j++) {
            float acc = 0.f;
            #pragma unroll
            for (int w = 0; w < 8; w++) acc += red[w][j];
            r[j] = acc;
        }
        const float invH = 1.0f / (float)H;
        float mu  = r[0] * invH;
        float var = fmaxf(r[1] * invH - mu * mu, 0.f);
        float rstd = rsqrtf(var + 1e-5f);
        float q0 = 3.0f / (1.0f + expf(-((r[2] - mu * r[5]) * rstd + sb[0])));
        float q1 = 3.0f / (1.0f + expf(-((r[3] - mu * r[6]) * rstd + sb[1])));
        float q2 = 3.0f / (1.0f + expf(-((r[4] - mu * r[7]) * rstd + sb[2])));

        const float rps = *rps_p;
        const float* pr = prior + (size_t)row * NB;
        float p[NB]; float psum = 0.f;
        #pragma unroll
        for (int i = 0; i < NB; i++) { p[i] = fmaxf(pr[i], 0.f); psum += p[i]; }
        float inv = 1.0f / fmaxf(psum, 1e-6f);

        float fused[NB];
        #pragma unroll
        for (int i = 0; i < NB; i++) {
            float cx = (float)(i & 3);
            float cy = (float)((i >> 2) & 3);
            float dx = q0 - cx, dy = q1 - cy, dz = q2;   // cz == 0 for NB=16
            float sp = expf(-0.5f * (dx * dx + dy * dy + dz * dz));
            float bias = logf(p[i] * inv + 1e-6f);
            bias = fminf(fmaxf(bias, -6.0f), 0.0f);
            fused[i] = sp + rps * bias;
        }
        // top-4 (descending, ties -> lowest index, same as lax.top_k)
        int   idx[TOPK]; float val[TOPK];
        #pragma unroll
        for (int k = 0; k < TOPK; k++) {
            int bi = 0; float bv = fused[0];
            #pragma unroll
            for (int i = 1; i < NB; i++)
                if (fused[i] > bv) { bv = fused[i]; bi = i; }
            idx[k] = bi; val[k] = bv; fused[bi] = -1e30f;
        }
        float mx = val[0];
        float e[TOPK], es = 0.f;
        #pragma unroll
        for (int k = 0; k < TOPK; k++) { e[k] = expf(val[k] - mx); es += e[k]; }
        float inve = 1.0f / es;
        #pragma unroll
        for (int k = 0; k < TOPK; k++) {
            int pos = atomicAdd(&g_counts[idx[k]], 1);
            if (pos < MAXROWS) {
                g_rows[idx[k] * MAXROWS + pos] = row;
                g_wts [idx[k] * MAXROWS + pos] = e[k] * inve;
            }
        }
    }
}

// ---------------------------------------------------------------------------
// Kernel 2: grouped gather-GEMM adapter.
// CTA = (block nb, tile of up to 128 rows that selected nb).
//   GEMM1: Lo[d][m] = sum_k down[nb][k][d] * Xa[k][m]       (k-major operands)
//   GEMM2: out[row_m][nb*256+n] += rs*w_m * sum_d Lo[d][m]*up[nb][d][n]
// 256 threads as 16x16 grid, 8x8 register micro-tiles.
// ---------------------------------------------------------------------------
__global__ void __launch_bounds__(256, 1) adapter_kernel(
    const float* __restrict__ x, const float* __restrict__ down,
    const float* __restrict__ up, const float* __restrict__ rs_p,
    float* __restrict__ out)
{
    const int nb = blockIdx.y;
    const int count = min(g_counts[nb], MAXROWS);
    const int m0 = blockIdx.x * MT;
    if (m0 >= count) return;
    const int M = min(MT, count - m0);

    extern __shared__ float smem[];
    float* Xa  = smem;                 // [BS=256][MT=128]  k-major  (128 KB)
    float* Lo  = Xa + BS * MT;         // [RANK=128][MT=128] k-major ( 64 KB)
    float* Bst = Lo + RANK * MT;       // [8][128] weight staging    (  4 KB)
    __shared__ int   rows_s[MT];
    __shared__ float wts_s[MT];

    const int tid = threadIdx.x;
    if (tid < MT) {
        if (tid < M) {
            rows_s[tid] = g_rows[nb * MAXROWS + m0 + tid];
            wts_s[tid]  = g_wts [nb * MAXROWS + m0 + tid];
        } else {
            rows_s[tid] = g_rows[nb * MAXROWS + m0];   // valid addr, zero weight
            wts_s[tid]  = 0.f;
        }
    }
    __syncthreads();

    // gather Xa (transposed into k-major smem)
    {
        const int m = tid >> 1, half = tid & 1;
        const float4* src = (const float4*)(x + (size_t)rows_s[m] * H + nb * BS + half * 128);
        #pragma unroll
        for (int j = 0; j < 32; j++) {
            float4 v = src[j];
            int k0 = half * 128 + j * 4;
            Xa[(k0 + 0) * MT + m] = v.x;
            Xa[(k0 + 1) * MT + m] = v.y;
            Xa[(k0 + 2) * MT + m] = v.z;
            Xa[(k0 + 3) * MT + m] = v.w;
        }
    }

    const int ty = tid >> 4, tx = tid & 15;

    // ---- GEMM1: Lo[d][m] (ty -> d tile, tx -> m tile) ----
    float acc[8][8];
    #pragma unroll
    for (int i = 0; i < 8; i++)
        #pragma unroll
        for (int j = 0; j < 8; j++) acc[i][j] = 0.f;

    const float* dwn = down + (size_t)nb * (BS * RANK);
    for (int kb = 0; kb < BS; kb += 8) {
        __syncthreads();
        ((float4*)Bst)[tid] = ((const float4*)(dwn + kb * RANK))[tid];  // 8x128
        __syncthreads();
        #pragma unroll
        for (int k = 0; k < 8; k++) {
            float a[8], b[8];
            *(float4*)&a[0] = *(const float4*)&Bst[k * RANK + ty * 8];
            *(float4*)&a[4] = *(const float4*)&Bst[k * RANK + ty * 8 + 4];
            *(float4*)&b[0] = *(const float4*)&Xa[(kb + k) * MT + tx * 8];
            *(float4*)&b[4] = *(const float4*)&Xa[(kb + k) * MT + tx * 8 + 4];
            #pragma unroll
            for (int i = 0; i < 8; i++)
                #pragma unroll
                for (int j = 0; j < 8; j++)
                    acc[i][j] += a[i] * b[j];
        }
    }
    __syncthreads();
    #pragma unroll
    for (int i = 0; i < 8; i++) {
        int d = ty * 8 + i;
        *(float4*)&Lo[d * MT + tx * 8 + 0] = make_float4(acc[i][0], acc[i][1], acc[i][2], acc[i][3]);
        *(float4*)&Lo[d * MT + tx * 8 + 4] = make_float4(acc[i][4], acc[i][5], acc[i][6], acc[i][7]);
    }

    // ---- GEMM2: out tile (ty -> m tile, tx -> n tile), two 128-col halves ----
    const float rs = *rs_p;
    const float* upw = up + (size_t)nb * (RANK * BS);
    for (int h = 0; h < 2; h++) {
        float acc2[8][8];
        #pragma unroll
        for (int i = 0; i < 8; i++)
            #pragma unroll
            for (int j = 0; j < 8; j++) acc2[i][j] = 0.f;

        for (int kb = 0; kb < RANK; kb += 8) {
            __syncthreads();
            {
                int r = tid >> 5, c = tid & 31;   // 8 rows x 32 float4 = 8x128
                ((float4*)Bst)[tid] = ((const float4*)(upw + (kb + r) * BS + h * 128))[c];
            }
            __syncthreads();
            #pragma unroll
            for (int k = 0; k < 8; k++) {
                float a[8], b[8];
                *(float4*)&a[0] = *(const float4*)&Lo[(kb + k) * MT + ty * 8];
                *(float4*)&a[4] = *(const float4*)&Lo[(kb + k) * MT + ty * 8 + 4];
                *(float4*)&b[0] = *(const float4*)&Bst[k * 128 + tx * 8];
                *(float4*)&b[4] = *(const float4*)&Bst[k * 128 + tx * 8 + 4];
                #pragma unroll
                for (int i = 0; i < 8; i++)
                    #pragma unroll
                    for (int j = 0; j < 8; j++)
                        acc2[i][j] += a[i] * b[j];
            }
        }
        // epilogue: out += rs * w * acc2   (out already holds hidden)
        #pragma unroll
        for (int i = 0; i < 8; i++) {
            int m = ty * 8 + i;
            if (m < M) {
                float scale = rs * wts_s[m];
                float* o = out + (size_t)rows_s[m] * H + nb * BS + h * 128 + tx * 8;
                float4 v0 = *(float4*)o;
                v0.x += scale * acc2[i][0]; v0.y += scale * acc2[i][1];
                v0.z += scale * acc2[i][2]; v0.w += scale * acc2[i][3];
                *(float4*)o = v0;
                float4 v1 = *(float4*)(o + 4);
                v1.x += scale * acc2[i][4]; v1.y += scale * acc2[i][5];
                v1.z += scale * acc2[i][6]; v1.w += scale * acc2[i][7];
                *(float4*)(o + 4) = v1;
            }
        }
    }
}

// ---------------------------------------------------------------------------
extern "C" void kernel_launch(void* const* d_in, const int* in_sizes, int n_in,
                              void* d_out, int out_size)
{
    const float* x     = (const float*)d_in[0];
    const float* prior = (const float*)d_in[1];
    const float* sw    = (const float*)d_in[2];
    const float* sb    = (const float*)d_in[3];
    const float* dw    = (const float*)d_in[4];
    const float* uw    = (const float*)d_in[5];
    const float* rps   = (const float*)d_in[6];
    const float* rs    = (const float*)d_in[7];
    float* out = (float*)d_out;

    int rows = in_sizes[0] / H;   // 8192
    if (rows > MAXROWS) rows = MAXROWS;

    int smem_bytes = (BS * MT + RANK * MT + 8 * 128) * (int)sizeof(float);  // 200704
    cudaFuncSetAttribute(adapter_kernel,
                         cudaFuncAttributeMaxDynamicSharedMemorySize, smem_bytes);

    zero_counts_kernel<<<1, 32>>>();
    route_kernel<<<rows, 256>>>(x, prior, sw, sb, rps, out);
    dim3 g2((rows + MT - 1) / MT, NB);
    adapter_kernel<<<g2, 256, smem_bytes>>>(x, dw, uw, rs, out);
}

// round 5
// speedup vs baseline: 1.2915x; 1.2915x over previous
#include <cuda_runtime.h>
#include <math.h>

#define H     4096
#define NB    16
#define BS    256
#define TOPK  4
#define RANK  128
#define MT    128
#define MAXROWS 8192

// ---- device-global scratch (no allocations allowed) ----
__device__ int   g_counts[NB];
__device__ int   g_rows[NB * MAXROWS];
__device__ float g_wts [NB * MAXROWS];

__global__ void zero_counts_kernel() {
    if (threadIdx.x < NB) g_counts[threadIdx.x] = 0;
}

__device__ __forceinline__ float warp_sum(float v) {
    v += __shfl_down_sync(0xffffffffu, v, 16);
    v += __shfl_down_sync(0xffffffffu, v, 8);
    v += __shfl_down_sync(0xffffffffu, v, 4);
    v += __shfl_down_sync(0xffffffffu, v, 2);
    v += __shfl_down_sync(0xffffffffu, v, 1);
    return v;
}

// ---------------------------------------------------------------------------
// Kernel 1: per-row routing + residual copy (out = hidden).
// ---------------------------------------------------------------------------
__global__ void __launch_bounds__(256) route_kernel(
    const float* __restrict__ x, const float* __restrict__ prior,
    const float* __restrict__ sw, const float* __restrict__ sb,
    const float* __restrict__ rps_p, float* __restrict__ out)
{
    const int row = blockIdx.x;
    const float4* xv = (const float4*)(x + (size_t)row * H);
    float4*       ov = (float4*)(out + (size_t)row * H);
    const float4* w0 = (const float4*)(sw);
    const float4* w1 = (const float4*)(sw + H);
    const float4* w2 = (const float4*)(sw + 2 * H);

    float s = 0.f, s2 = 0.f, d0 = 0.f, d1 = 0.f, d2 = 0.f;
    float t0 = 0.f, t1 = 0.f, t2 = 0.f;

    #pragma unroll 4
    for (int i = threadIdx.x; i < H / 4; i += 256) {
        float4 v = xv[i];
        ov[i] = v;                       // fused residual copy
        float4 a = __ldg(&w0[i]);
        float4 b = __ldg(&w1[i]);
        float4 c = __ldg(&w2[i]);
        s  += (v.x + v.y) + (v.z + v.w);
        s2 += v.x * v.x + v.y * v.y + v.z * v.z + v.w * v.w;
        d0 += v.x * a.x + v.y * a.y + v.z * a.z + v.w * a.w;
        d1 += v.x * b.x + v.y * b.y + v.z * b.z + v.w * b.w;
        d2 += v.x * c.x + v.y * c.y + v.z * c.z + v.w * c.w;
        t0 += (a.x + a.y) + (a.z + a.w);
        t1 += (b.x + b.y) + (b.z + b.w);
        t2 += (c.x + c.y) + (c.z + c.w);
    }

    float vals[8] = {s, s2, d0, d1, d2, t0, t1, t2};
    __shared__ float red[8][8];
    const int wid = threadIdx.x >> 5, lane = threadIdx.x & 31;
    #pragma unroll
    for (int j = 0; j < 8; j++) vals[j] = warp_sum(vals[j]);
    if (lane == 0) {
        #pragma unroll
        for (int j = 0; j < 8; j++) red[wid][j] = vals[j];
    }
    __syncthreads();

    if (threadIdx.x == 0) {
        float r[8];
        #pragma unroll
        for (int j = 0; j < 8; j++) {
            float acc = 0.f;
            #pragma unroll
            for (int w = 0; w < 8; w++) acc += red[w][j];
            r[j] = acc;
        }
        const float invH = 1.0f / (float)H;
        float mu  = r[0] * invH;
        float var = fmaxf(r[1] * invH - mu * mu, 0.f);
        float rstd = rsqrtf(var + 1e-5f);
        float q0 = 3.0f / (1.0f + expf(-((r[2] - mu * r[5]) * rstd + sb[0])));
        float q1 = 3.0f / (1.0f + expf(-((r[3] - mu * r[6]) * rstd + sb[1])));
        float q2 = 3.0f / (1.0f + expf(-((r[4] - mu * r[7]) * rstd + sb[2])));

        const float rps = *rps_p;
        const float* pr = prior + (size_t)row * NB;
        float p[NB]; float psum = 0.f;
        #pragma unroll
        for (int i = 0; i < NB; i++) { p[i] = fmaxf(pr[i], 0.f); psum += p[i]; }
        float inv = 1.0f / fmaxf(psum, 1e-6f);

        float fused[NB];
        #pragma unroll
        for (int i = 0; i < NB; i++) {
            float cx = (float)(i & 3);
            float cy = (float)((i >> 2) & 3);
            float dx = q0 - cx, dy = q1 - cy, dz = q2;   // cz == 0 for NB=16
            float sp = expf(-0.5f * (dx * dx + dy * dy + dz * dz));
            float bias = logf(p[i] * inv + 1e-6f);
            bias = fminf(fmaxf(bias, -6.0f), 0.0f);
            fused[i] = sp + rps * bias;
        }
        int   idx[TOPK]; float val[TOPK];
        #pragma unroll
        for (int k = 0; k < TOPK; k++) {
            int bi = 0; float bv = fused[0];
            #pragma unroll
            for (int i = 1; i < NB; i++)
                if (fused[i] > bv) { bv = fused[i]; bi = i; }
            idx[k] = bi; val[k] = bv; fused[bi] = -1e30f;
        }
        float mx = val[0];
        float e[TOPK], es = 0.f;
        #pragma unroll
        for (int k = 0; k < TOPK; k++) { e[k] = expf(val[k] - mx); es += e[k]; }
        float inve = 1.0f / es;
        #pragma unroll
        for (int k = 0; k < TOPK; k++) {
            int pos = atomicAdd(&g_counts[idx[k]], 1);
            if (pos < MAXROWS) {
                g_rows[idx[k] * MAXROWS + pos] = row;
                g_wts [idx[k] * MAXROWS + pos] = e[k] * inve;
            }
        }
    }
}

// ---------------------------------------------------------------------------
// Kernel 2: grouped gather-GEMM adapter. 104KB smem -> 2 CTAs/SM.
// Xa gathered in 4 chunks of 64 k; weight stages ping-pong with register
// prefetch (one __syncthreads per k-block).
// ---------------------------------------------------------------------------
__global__ void __launch_bounds__(256, 2) adapter_kernel(
    const float* __restrict__ x, const float* __restrict__ down,
    const float* __restrict__ up, const float* __restrict__ rs_p,
    float* __restrict__ out)
{
    const int nb = blockIdx.y;
    const int count = min(g_counts[nb], MAXROWS);
    const int m0 = blockIdx.x * MT;
    if (m0 >= count) return;
    const int M = min(MT, count - m0);

    extern __shared__ float smem[];
    float* Xa  = smem;                 // [64][MT=128] chunk, k-major (32 KB)
    float* Lo  = Xa + 64 * MT;         // [RANK=128][MT=128]          (64 KB)
    float* Bst = Lo + RANK * MT;       // 2 x 1024 ping-pong stages    (8 KB)
    __shared__ int   rows_s[MT];
    __shared__ float wts_s[MT];

    const int tid = threadIdx.x;
    if (tid < MT) {
        if (tid < M) {
            rows_s[tid] = g_rows[nb * MAXROWS + m0 + tid];
            wts_s[tid]  = g_wts [nb * MAXROWS + m0 + tid];
        } else {
            rows_s[tid] = g_rows[nb * MAXROWS + m0];   // valid addr, zero weight
            wts_s[tid]  = 0.f;
        }
    }

    const float* dwn = down + (size_t)nb * (BS * RANK);
    const float* upw = up   + (size_t)nb * (RANK * BS);

    const int ty = tid >> 4, tx = tid & 15;
    const int gm = tid & 127, seg = tid >> 7;     // gather: row gm, k-seg

    // prefetch first down-weight stage (8 k x 128 d = 1024 floats)
    float4 w = ((const float4*)dwn)[tid];

    float acc[8][8];
    #pragma unroll
    for (int i = 0; i < 8; i++)
        #pragma unroll
        for (int j = 0; j < 8; j++) acc[i][j] = 0.f;

    int p = 0;

    // ---- GEMM1: Lo[d][m] = sum_k down[k][d] * Xa[k][m], chunked over k ----
    for (int kc = 0; kc < 4; kc++) {
        __syncthreads();   // prev chunk compute done (and rows_s visible at kc=0)
        {   // gather chunk: 64 k x 128 m ; thread -> (row gm, k in [seg*32,+32))
            const float4* src = (const float4*)(x + (size_t)rows_s[gm] * H
                                                + nb * BS + kc * 64 + seg * 32);
            float4 g0 = src[0], g1 = src[1], g2 = src[2], g3 = src[3];
            int kb = seg * 32;
            Xa[(kb+ 0)*MT+gm]=g0.x; Xa[(kb+ 1)*MT+gm]=g0.y; Xa[(kb+ 2)*MT+gm]=g0.z; Xa[(kb+ 3)*MT+gm]=g0.w;
            Xa[(kb+ 4)*MT+gm]=g1.x; Xa[(kb+ 5)*MT+gm]=g1.y; Xa[(kb+ 6)*MT+gm]=g1.z; Xa[(kb+ 7)*MT+gm]=g1.w;
            Xa[(kb+ 8)*MT+gm]=g2.x; Xa[(kb+ 9)*MT+gm]=g2.y; Xa[(kb+10)*MT+gm]=g2.z; Xa[(kb+11)*MT+gm]=g2.w;
            Xa[(kb+12)*MT+gm]=g3.x; Xa[(kb+13)*MT+gm]=g3.y; Xa[(kb+14)*MT+gm]=g3.z; Xa[(kb+15)*MT+gm]=g3.w;
            float4 g4 = src[4], g5 = src[5], g6 = src[6], g7 = src[7];
            Xa[(kb+16)*MT+gm]=g4.x; Xa[(kb+17)*MT+gm]=g4.y; Xa[(kb+18)*MT+gm]=g4.z; Xa[(kb+19)*MT+gm]=g4.w;
            Xa[(kb+20)*MT+gm]=g5.x; Xa[(kb+21)*MT+gm]=g5.y; Xa[(kb+22)*MT+gm]=g5.z; Xa[(kb+23)*MT+gm]=g5.w;
            Xa[(kb+24)*MT+gm]=g6.x; Xa[(kb+25)*MT+gm]=g6.y; Xa[(kb+26)*MT+gm]=g6.z; Xa[(kb+27)*MT+gm]=g6.w;
            Xa[(kb+28)*MT+gm]=g7.x; Xa[(kb+29)*MT+gm]=g7.y; Xa[(kb+30)*MT+gm]=g7.z; Xa[(kb+31)*MT+gm]=g7.w;
        }
        for (int b8 = 0; b8 < 8; b8++) {
            ((float4*)(Bst + p * 1024))[tid] = w;
            __syncthreads();
            int nxt = kc * 8 + b8 + 1;
            if (nxt < 32) {
                w = ((const float4*)(dwn + nxt * 8 * RANK))[tid];
            } else {
                // prefetch first up-weight stage for GEMM2 (h=0, kb=0)
                w = ((const float4*)(upw + (tid >> 5) * BS))[tid & 31];
            }
            const float* Bp = Bst + p * 1024;
            #pragma unroll
            for (int k = 0; k < 8; k++) {
                float a[8], b[8];
                *(float4*)&a[0] = *(const float4*)&Bp[k * RANK + ty * 8];
                *(float4*)&a[4] = *(const float4*)&Bp[k * RANK + ty * 8 + 4];
                *(float4*)&b[0] = *(const float4*)&Xa[(b8 * 8 + k) * MT + tx * 8];
                *(float4*)&b[4] = *(const float4*)&Xa[(b8 * 8 + k) * MT + tx * 8 + 4];
                #pragma unroll
                for (int i = 0; i < 8; i++)
                    #pragma unroll
                    for (int j = 0; j < 8; j++)
                        acc[i][j] += a[i] * b[j];
            }
            p ^= 1;
        }
    }

    // write Lo (own elements), then barrier for GEMM2 reads + Bst reuse
    #pragma unroll
    for (int i = 0; i < 8; i++) {
        int d = ty * 8 + i;
        *(float4*)&Lo[d * MT + tx * 8 + 0] = make_float4(acc[i][0], acc[i][1], acc[i][2], acc[i][3]);
        *(float4*)&Lo[d * MT + tx * 8 + 4] = make_float4(acc[i][4], acc[i][5], acc[i][6], acc[i][7]);
    }
    __syncthreads();

    // ---- GEMM2: out[m][n] += rs*w_m * sum_d Lo[d][m]*up[d][n], halves of 128 n ----
    const float rs = *rs_p;
    for (int h = 0; h < 2; h++) {
        float acc2[8][8];
        #pragma unroll
        for (int i = 0; i < 8; i++)
            #pragma unroll
            for (int j = 0; j < 8; j++) acc2[i][j] = 0.f;

        for (int b8 = 0; b8 < 16; b8++) {
            ((float4*)(Bst + p * 1024))[tid] = w;
            __syncthreads();
            int t = h * 16 + b8 + 1;
            if (t < 32) {
                w = ((const float4*)(upw + ((t & 15) * 8 + (tid >> 5)) * BS
                                     + (t >> 4) * 128))[tid & 31];
            }
            const float* Bp = Bst + p * 1024;
            #pragma unroll
            for (int k = 0; k < 8; k++) {
                float a[8], b[8];
                *(float4*)&a[0] = *(const float4*)&Lo[(b8 * 8 + k) * MT + ty * 8];
                *(float4*)&a[4] = *(const float4*)&Lo[(b8 * 8 + k) * MT + ty * 8 + 4];
                *(float4*)&b[0] = *(const float4*)&Bp[k * 128 + tx * 8];
                *(float4*)&b[4] = *(const float4*)&Bp[k * 128 + tx * 8 + 4];
                #pragma unroll
                for (int i = 0; i < 8; i++)
                    #pragma unroll
                    for (int j = 0; j < 8; j++)
                        acc2[i][j] += a[i] * b[j];
            }
            p ^= 1;
        }
        // epilogue: out += rs * w_m * acc2   (out already holds hidden)
        #pragma unroll
        for (int i = 0; i < 8; i++) {
            int m = ty * 8 + i;
            if (m < M) {
                float scale = rs * wts_s[m];
                float* o = out + (size_t)rows_s[m] * H + nb * BS + h * 128 + tx * 8;
                float4 v0 = *(float4*)o;
                v0.x += scale * acc2[i][0]; v0.y += scale * acc2[i][1];
                v0.z += scale * acc2[i][2]; v0.w += scale * acc2[i][3];
                *(float4*)o = v0;
                float4 v1 = *(float4*)(o + 4);
                v1.x += scale * acc2[i][4]; v1.y += scale * acc2[i][5];
                v1.z += scale * acc2[i][6]; v1.w += scale * acc2[i][7];
                *(float4*)(o + 4) = v1;
            }
        }
    }
}

// ---------------------------------------------------------------------------
extern "C" void kernel_launch(void* const* d_in, const int* in_sizes, int n_in,
                              void* d_out, int out_size)
{
    const float* x     = (const float*)d_in[0];
    const float* prior = (const float*)d_in[1];
    const float* sw    = (const float*)d_in[2];
    const float* sb    = (const float*)d_in[3];
    const float* dw    = (const float*)d_in[4];
    const float* uw    = (const float*)d_in[5];
    const float* rps   = (const float*)d_in[6];
    const float* rs    = (const float*)d_in[7];
    float* out = (float*)d_out;

    int rows = in_sizes[0] / H;   // 8192
    if (rows > MAXROWS) rows = MAXROWS;

    int smem_bytes = (64 * MT + RANK * MT + 2 * 1024) * (int)sizeof(float);  // 106496
    cudaFuncSetAttribute(adapter_kernel,
                         cudaFuncAttributeMaxDynamicSharedMemorySize, smem_bytes);

    zero_counts_kernel<<<1, 32>>>();
    route_kernel<<<rows, 256>>>(x, prior, sw, sb, rps, out);
    dim3 g2((rows + MT - 1) / MT, NB);
    adapter_kernel<<<g2, 256, smem_bytes>>>(x, dw, uw, rs, out);
}